// round 1
// baseline (speedup 1.0000x reference)
#include <cuda_runtime.h>

#define VOCAB 32000
#define EMB   512
#define TT    20
#define BB    64
#define TS    (TT - 1)    // 19 LSTM steps
#define G4    (4 * EMB)   // 2048 gate width

// ---------------- scratch (device globals; no allocation allowed) ----------
__device__ float g_x[TS * BB * EMB];      // time-major LSTM inputs  [t][b][e]
__device__ float g_seq[BB * TT * EMB];    // [b][t][e]: emb[:,0], h_1..h_19
__device__ float g_xg[TS * BB * G4];      // precomputed x @ W_ih^T + biases
__device__ float g_gates[BB * G4];        // per-step gate buffer
__device__ float g_h[BB * EMB];
__device__ float g_c[BB * EMB];

// ---------------- embedding gather: g_x[t][b][:] = W_emb[captions[b][t]] ---
__global__ void k_embed(const float* __restrict__ W_emb,
                        const int* __restrict__ captions) {
    int idx = blockIdx.x * blockDim.x + threadIdx.x;
    if (idx >= TS * BB * EMB) return;
    int e = idx & (EMB - 1);
    int b = (idx >> 9) & 63;
    int t = idx >> 15;
    int tok = captions[b * TT + t];
    g_x[idx] = W_emb[tok * EMB + e];
}

// ---------------- init: h=0, c=features, seq[:,0]=emb[:,0] -----------------
__global__ void k_init(const float* __restrict__ features) {
    int idx = blockIdx.x * blockDim.x + threadIdx.x;
    if (idx >= BB * EMB) return;
    g_h[idx] = 0.0f;
    g_c[idx] = features[idx];
    int b = idx >> 9, e = idx & 511;
    g_seq[(b * TT) * EMB + e] = g_x[b * EMB + e];  // g_x slice t=0
}

// ---------------- tiled fp32 NT GEMM: C[m,n] = sum_k A[m,k]*B[n,k] (+adds) -
// All problem dims divide the tiles -> no bounds checks.
template <int BM, int BN, int BK, int TM, int TN>
__global__ void gemm_nt(const float* __restrict__ A, int lda,
                        const float* __restrict__ B, int ldb,
                        float* __restrict__ C, int ldc,
                        const float* __restrict__ add_src,   // C-shaped or null
                        const float* __restrict__ bias_a,    // per-n or null
                        const float* __restrict__ bias_b,    // per-n or null
                        int K) {
    __shared__ float As[BK][BM + 1];
    __shared__ float Bs[BK][BN + 1];
    constexpr int THREADS = (BM / TM) * (BN / TN);

    int tid = threadIdx.x;
    int tn  = tid % (BN / TN);
    int tm  = tid / (BN / TN);
    int m0  = blockIdx.y * BM;
    int n0  = blockIdx.x * BN;
    const float* Ab = A + (long)m0 * lda;
    const float* Bb = B + (long)n0 * ldb;

    float acc[TM][TN] = {};

    for (int kk = 0; kk < K; kk += BK) {
        // load A tile (BM x BK), store transposed for conflict-light reads
        #pragma unroll 2
        for (int i = tid; i < BM * BK / 4; i += THREADS) {
            int r  = i / (BK / 4);
            int c4 = i % (BK / 4);
            float4 v = *(const float4*)(Ab + (long)r * lda + kk + c4 * 4);
            As[c4 * 4 + 0][r] = v.x;
            As[c4 * 4 + 1][r] = v.y;
            As[c4 * 4 + 2][r] = v.z;
            As[c4 * 4 + 3][r] = v.w;
        }
        #pragma unroll 2
        for (int i = tid; i < BN * BK / 4; i += THREADS) {
            int r  = i / (BK / 4);
            int c4 = i % (BK / 4);
            float4 v = *(const float4*)(Bb + (long)r * ldb + kk + c4 * 4);
            Bs[c4 * 4 + 0][r] = v.x;
            Bs[c4 * 4 + 1][r] = v.y;
            Bs[c4 * 4 + 2][r] = v.z;
            Bs[c4 * 4 + 3][r] = v.w;
        }
        __syncthreads();

        #pragma unroll
        for (int k = 0; k < BK; k++) {
            float ar[TM], br[TN];
            #pragma unroll
            for (int i = 0; i < TM; i++) ar[i] = As[k][tm * TM + i];
            #pragma unroll
            for (int j = 0; j < TN; j++) br[j] = Bs[k][tn * TN + j];
            #pragma unroll
            for (int i = 0; i < TM; i++)
                #pragma unroll
                for (int j = 0; j < TN; j++)
                    acc[i][j] += ar[i] * br[j];
        }
        __syncthreads();
    }

    #pragma unroll
    for (int i = 0; i < TM; i++) {
        int m = m0 + tm * TM + i;
        #pragma unroll
        for (int j = 0; j < TN; j++) {
            int n = n0 + tn * TN + j;
            float v = acc[i][j];
            if (add_src) v += add_src[(long)m * ldc + n];
            if (bias_a)  v += bias_a[n];
            if (bias_b)  v += bias_b[n];
            C[(long)m * ldc + n] = v;
        }
    }
}

// ---------------- LSTM pointwise cell update -------------------------------
__device__ __forceinline__ float sigf(float x) { return 1.0f / (1.0f + expf(-x)); }

__global__ void k_update(int t) {
    int idx = blockIdx.x * blockDim.x + threadIdx.x;
    if (idx >= BB * EMB) return;
    int b = idx >> 9, j = idx & 511;
    const float* gr = g_gates + b * G4;
    float i_ = sigf(gr[j]);
    float f_ = sigf(gr[512 + j]);
    float gg = tanhf(gr[1024 + j]);
    float o_ = sigf(gr[1536 + j]);
    float c  = f_ * g_c[idx] + i_ * gg;
    float h  = o_ * tanhf(c);
    g_c[idx] = c;
    g_h[idx] = h;
    g_seq[(b * TT + t + 1) * EMB + j] = h;
}

// ---------------- launch ---------------------------------------------------
extern "C" void kernel_launch(void* const* d_in, const int* in_sizes, int n_in,
                              void* d_out, int out_size) {
    const float* features = (const float*)d_in[0];
    const int*   captions = (const int*)d_in[1];
    const float* W_emb    = (const float*)d_in[2];
    const float* W_out    = (const float*)d_in[3];
    const float* b_out    = (const float*)d_in[4];
    const float* W_ih     = (const float*)d_in[5];
    const float* W_hh     = (const float*)d_in[6];
    const float* b_ih     = (const float*)d_in[7];
    const float* b_hh     = (const float*)d_in[8];
    float* out = (float*)d_out;

    float *px, *pseq, *pxg, *pgates, *ph;
    cudaGetSymbolAddress((void**)&px,     g_x);
    cudaGetSymbolAddress((void**)&pseq,   g_seq);
    cudaGetSymbolAddress((void**)&pxg,    g_xg);
    cudaGetSymbolAddress((void**)&pgates, g_gates);
    cudaGetSymbolAddress((void**)&ph,     g_h);

    // 1) gather embeddings (time-major) + init state
    k_embed<<<(TS * BB * EMB + 255) / 256, 256>>>(W_emb, captions);
    k_init<<<(BB * EMB + 255) / 256, 256>>>(features);

    // 2) Xg = X @ W_ih^T + b_ih + b_hh   (M=1216, N=2048, K=512)
    {
        dim3 grid(G4 / 64, (TS * BB) / 64);
        gemm_nt<64, 64, 16, 4, 4><<<grid, 256>>>(
            px, EMB, W_ih, EMB, pxg, G4, nullptr, b_ih, b_hh, EMB);
    }

    // 3) recurrent chain: gates = Xg[t] + h @ W_hh^T; then cell update
    for (int t = 0; t < TS; t++) {
        dim3 grid(G4 / 32, 1);  // M=64, N=2048
        gemm_nt<64, 32, 16, 2, 4><<<grid, 256>>>(
            ph, EMB, W_hh, EMB, pgates, G4,
            pxg + (long)t * BB * G4, nullptr, nullptr, EMB);
        k_update<<<(BB * EMB + 255) / 256, 256>>>(t);
    }

    // 4) logits = seq @ W_out^T + b_out  (M=1280, N=32000, K=512)
    {
        dim3 grid(VOCAB / 64, (BB * TT) / 64);
        gemm_nt<64, 64, 16, 4, 4><<<grid, 256>>>(
            pseq, EMB, W_out, EMB, out, VOCAB, nullptr, b_out, nullptr, EMB);
    }
}

// round 16
// speedup vs baseline: 2.9434x; 2.9434x over previous
#include <cuda_runtime.h>
#include <cuda_bf16.h>
#include <cstdint>

#define VOCAB 32000
#define EMB   512
#define TT    20
#define BB    64
#define TS    19
#define G4    2048
#define KP    1536          // split-bf16 concatenated K (3 x 512)
#define MR    1280          // padded row count (>=1216, mult of 128)
#define NKC   16            // k-split chunks for recurrent gemm (512/32)
#define NCH64 (KP / 64)     // 24 K-stages of 64

// ---------------- device scratch (static globals; allocation-guard-safe) ---
__device__ __align__(128) float g_x[MR * EMB];          // time-major LSTM inputs
__device__ __align__(128) float g_seq[MR * EMB];        // [b][t][e]
__device__ __align__(128) float g_xg[MR * G4];          // x@W_ih^T + b_ih + b_hh
__device__ __align__(128) float g_part[NKC * BB * G4];  // k-split partials
__device__ __align__(128) float g_h[BB * EMB];
__device__ __align__(128) float g_c[BB * EMB];
__device__ __align__(128) float g_bias2[G4];
__device__ __align__(128) __nv_bfloat16 g_xa[MR * KP];
__device__ __align__(128) __nv_bfloat16 g_seqa[MR * KP];
__device__ __align__(128) __nv_bfloat16 g_wih3[G4 * KP];
__device__ __align__(128) __nv_bfloat16 g_wout3[VOCAB * KP];

// ---------------- helpers ---------------------------------------------------
__device__ __forceinline__ uint32_t smem_u32(const void* p) {
    uint32_t a;
    asm("{ .reg .u64 t; cvta.to.shared.u64 t, %1; cvt.u32.u64 %0, t; }" : "=r"(a) : "l"(p));
    return a;
}
#define SWZ(o) ((o) ^ (((o) >> 3) & 0x70))

__device__ __forceinline__ void ldsm4(uint32_t& r0, uint32_t& r1, uint32_t& r2, uint32_t& r3,
                                      uint32_t addr) {
    asm volatile("ldmatrix.sync.aligned.m8n8.x4.shared.b16 {%0,%1,%2,%3}, [%4];"
                 : "=r"(r0), "=r"(r1), "=r"(r2), "=r"(r3) : "r"(addr));
}
__device__ __forceinline__ void mma16816(float* d, const uint32_t* a, uint32_t b0, uint32_t b1) {
    asm volatile(
        "mma.sync.aligned.m16n8k16.row.col.f32.bf16.bf16.f32 "
        "{%0,%1,%2,%3}, {%4,%5,%6,%7}, {%8,%9}, {%0,%1,%2,%3};"
        : "+f"(d[0]), "+f"(d[1]), "+f"(d[2]), "+f"(d[3])
        : "r"(a[0]), "r"(a[1]), "r"(a[2]), "r"(a[3]), "r"(b0), "r"(b1));
}

// ---------------- prep kernels ---------------------------------------------
__global__ void k_embed(const float* __restrict__ W_emb,
                        const int* __restrict__ captions) {
    int idx = blockIdx.x * blockDim.x + threadIdx.x;
    if (idx >= TS * BB * EMB) return;
    int e = idx & (EMB - 1);
    int b = (idx >> 9) & 63;
    int t = idx >> 15;
    int tok = captions[b * TT + t];
    g_x[idx] = W_emb[tok * EMB + e];
}

__global__ void k_init(const float* __restrict__ features) {
    int idx = blockIdx.x * blockDim.x + threadIdx.x;
    if (idx >= BB * EMB) return;
    g_h[idx] = 0.0f;
    g_c[idx] = features[idx];
    int b = idx >> 9, e = idx & 511;
    g_seq[(b * TT) * EMB + e] = g_x[b * EMB + e];  // t=0 slice of time-major g_x
}

__global__ void k_bias2(const float* __restrict__ b_ih, const float* __restrict__ b_hh) {
    int i = blockIdx.x * blockDim.x + threadIdx.x;
    if (i < G4) g_bias2[i] = b_ih[i] + b_hh[i];
}

// split fp32 -> concatenated bf16 triple.  modeB=0: [hi|lo|hi]  modeB=1: [hi|hi|lo]
__global__ void k_convert(const float* __restrict__ src, __nv_bfloat16* __restrict__ dst,
                          int rows_valid, int total_rows, int modeB) {
    int idx = blockIdx.x * blockDim.x + threadIdx.x;
    if (idx >= total_rows * EMB) return;
    int r = idx >> 9, c = idx & 511;
    float v = (r < rows_valid) ? src[idx] : 0.0f;
    __nv_bfloat16 hi = __float2bfloat16(v);
    __nv_bfloat16 lo = __float2bfloat16(v - __bfloat162float(hi));
    __nv_bfloat16* row = dst + (size_t)r * KP;
    row[c] = hi;
    row[512 + c]  = modeB ? hi : lo;
    row[1024 + c] = modeB ? lo : hi;
}

// ---------------- bf16 warp-MMA GEMM: C = A[M,KP] @ B[N,KP]^T + bias -------
// CTA tile 128x128, BK=64, 256 threads (8 warps; warp tile 32x64).
// 3-stage cp.async pipeline; SW128-swizzled 128B-row smem tiles; ldmatrix.
__global__ void __launch_bounds__(256, 1)
mma_gemm(const __nv_bfloat16* __restrict__ A,
         const __nv_bfloat16* __restrict__ B,
         float* __restrict__ C, size_t ldc,
         const float* __restrict__ bias) {
    extern __shared__ char smraw[];
    uint32_t base = (smem_u32(smraw) + 127) & ~127u;
    const int tid  = threadIdx.x;
    const int lane = tid & 31;
    const int wid  = tid >> 5;
    const int wm   = (wid >> 1) * 32;   // warp m offset in CTA tile
    const int wn   = (wid & 1) * 64;    // warp n offset
    const int m0   = blockIdx.y * 128;
    const int n0   = blockIdx.x * 128;

    const __nv_bfloat16* Ab = A + (size_t)m0 * KP;
    const __nv_bfloat16* Bb = B + (size_t)n0 * KP;

    float acc[2][8][4];
    #pragma unroll
    for (int i = 0; i < 2; i++)
        #pragma unroll
        for (int j = 0; j < 8; j++)
            #pragma unroll
            for (int q = 0; q < 4; q++) acc[i][j][q] = 0.0f;

    // issue one 64-wide K stage into buffer s%3 (A 16KB + B 16KB per stage)
    auto issue = [&](int s) {
        uint32_t sA = base + (s % 3) * 32768;
        uint32_t sB = sA + 16384;
        const __nv_bfloat16* Ag = Ab + s * 64;
        const __nv_bfloat16* Bg = Bb + s * 64;
        #pragma unroll
        for (int u = 0; u < 4; u++) {
            int i = u * 256 + tid;
            int r = i >> 3, cch = i & 7;
            uint32_t d = sA + SWZ(r * 128 + cch * 16);
            const void* g = Ag + (size_t)r * KP + cch * 8;
            asm volatile("cp.async.cg.shared.global [%0], [%1], 16;" :: "r"(d), "l"(g) : "memory");
        }
        #pragma unroll
        for (int u = 0; u < 4; u++) {
            int i = u * 256 + tid;
            int r = i >> 3, cch = i & 7;
            uint32_t d = sB + SWZ(r * 128 + cch * 16);
            const void* g = Bg + (size_t)r * KP + cch * 8;
            asm volatile("cp.async.cg.shared.global [%0], [%1], 16;" :: "r"(d), "l"(g) : "memory");
        }
        asm volatile("cp.async.commit_group;" ::: "memory");
    };

    issue(0);
    issue(1);

    for (int s = 0; s < NCH64; s++) {
        if (s + 2 < NCH64) {
            issue(s + 2);
            asm volatile("cp.async.wait_group 2;" ::: "memory");
        } else if (s + 1 < NCH64) {
            asm volatile("cp.async.wait_group 1;" ::: "memory");
        } else {
            asm volatile("cp.async.wait_group 0;" ::: "memory");
        }
        __syncthreads();

        uint32_t sA = base + (s % 3) * 32768;
        uint32_t sB = sA + 16384;
        #pragma unroll
        for (int ks = 0; ks < 4; ks++) {
            int c0 = ks * 2;
            uint32_t af[2][4], bf[4][4];
            #pragma unroll
            for (int i = 0; i < 2; i++) {
                int row = wm + i * 16 + (lane & 15);
                int cch = c0 + (lane >> 4);
                ldsm4(af[i][0], af[i][1], af[i][2], af[i][3],
                      sA + SWZ(row * 128 + cch * 16));
            }
            #pragma unroll
            for (int j = 0; j < 4; j++) {
                int row = wn + j * 16 + (lane & 15);
                int cch = c0 + (lane >> 4);
                ldsm4(bf[j][0], bf[j][1], bf[j][2], bf[j][3],
                      sB + SWZ(row * 128 + cch * 16));
            }
            #pragma unroll
            for (int i = 0; i < 2; i++)
                #pragma unroll
                for (int jj = 0; jj < 8; jj++) {
                    uint32_t b0 = (jj & 1) ? bf[jj >> 1][1] : bf[jj >> 1][0];
                    uint32_t b1 = (jj & 1) ? bf[jj >> 1][3] : bf[jj >> 1][2];
                    mma16816(acc[i][jj], af[i], b0, b1);
                }
        }
        __syncthreads();
    }

    // epilogue: d{0,1} -> (row, col..col+1); d{2,3} -> (row+8, ...)
    #pragma unroll
    for (int i = 0; i < 2; i++) {
        int row = m0 + wm + i * 16 + (lane >> 2);
        #pragma unroll
        for (int j = 0; j < 8; j++) {
            int col = n0 + wn + j * 8 + (lane & 3) * 2;
            float2 bv = *(const float2*)(bias + col);
            float2 o0 = { acc[i][j][0] + bv.x, acc[i][j][1] + bv.y };
            float2 o1 = { acc[i][j][2] + bv.x, acc[i][j][3] + bv.y };
            *(float2*)(C + (size_t)row * ldc + col) = o0;
            *(float2*)(C + (size_t)(row + 8) * ldc + col) = o1;
        }
    }
}

// ---------------- recurrent step: k-split partial GEMM ---------------------
// grid = 128 CTAs = (8 n-tiles of 256) x (16 k-chunks of 32). 256 threads.
__global__ void __launch_bounds__(256) k_step(const float* __restrict__ Whh) {
    __shared__ float wst[32][260];   // [k][n] transposed, padded
    __shared__ float hst[32][72];    // [k][b] transposed, padded
    int tid = threadIdx.x;
    int kc = blockIdx.x >> 3;
    int n0 = (blockIdx.x & 7) * 256;
    int kbase = kc * 32;

    #pragma unroll
    for (int q = 0; q < 8; q++) {                      // W chunk: 256 x 32
        int i = q * 256 + tid;
        int r = i >> 3, k4 = i & 7;
        float4 v = *(const float4*)&Whh[(size_t)(n0 + r) * EMB + kbase + k4 * 4];
        wst[k4 * 4 + 0][r] = v.x;
        wst[k4 * 4 + 1][r] = v.y;
        wst[k4 * 4 + 2][r] = v.z;
        wst[k4 * 4 + 3][r] = v.w;
    }
    {                                                  // h chunk: 64 x 32
        int i = tid;
        if (i < 512) {
            int b = i >> 3, k4 = i & 7;
            float4 v = *(const float4*)&g_h[b * EMB + kbase + k4 * 4];
            hst[k4 * 4 + 0][b] = v.x;
            hst[k4 * 4 + 1][b] = v.y;
            hst[k4 * 4 + 2][b] = v.z;
            hst[k4 * 4 + 3][b] = v.w;
        }
        i = tid + 256;
        if (i < 512) {
            int b = i >> 3, k4 = i & 7;
            float4 v = *(const float4*)&g_h[b * EMB + kbase + k4 * 4];
            hst[k4 * 4 + 0][b] = v.x;
            hst[k4 * 4 + 1][b] = v.y;
            hst[k4 * 4 + 2][b] = v.z;
            hst[k4 * 4 + 3][b] = v.w;
        }
    }
    __syncthreads();

    int l = tid & 31, bg = tid >> 5;                   // b = bg + 8*i, n = n0 + l + 32*j
    float acc[8][8] = {};
    #pragma unroll 4
    for (int k = 0; k < 32; k++) {
        float hv[8], wv[8];
        #pragma unroll
        for (int i = 0; i < 8; i++) hv[i] = hst[k][bg + 8 * i];
        #pragma unroll
        for (int j = 0; j < 8; j++) wv[j] = wst[k][l + 32 * j];
        #pragma unroll
        for (int i = 0; i < 8; i++)
            #pragma unroll
            for (int j = 0; j < 8; j++)
                acc[i][j] += hv[i] * wv[j];
    }
    #pragma unroll
    for (int i = 0; i < 8; i++) {
        int b = bg + 8 * i;
        float* dst = g_part + (size_t)(kc * BB + b) * G4 + n0;
        #pragma unroll
        for (int j = 0; j < 8; j++) dst[l + 32 * j] = acc[i][j];
    }
}

// ---------------- fused reduce + LSTM cell update --------------------------
__device__ __forceinline__ float sigf(float x) { return 1.0f / (1.0f + expf(-x)); }

__global__ void k_update(int t) {
    int idx = blockIdx.x * blockDim.x + threadIdx.x;
    if (idx >= BB * EMB) return;
    int b = idx >> 9, j = idx & 511;
    const float* xg = g_xg + (size_t)(t * BB + b) * G4;
    float gi = xg[j], gf = xg[512 + j], gg = xg[1024 + j], go = xg[1536 + j];
    #pragma unroll
    for (int kc = 0; kc < NKC; kc++) {
        const float* p = g_part + (size_t)(kc * BB + b) * G4;
        gi += p[j];
        gf += p[512 + j];
        gg += p[1024 + j];
        go += p[1536 + j];
    }
    float i_ = sigf(gi), f_ = sigf(gf), g_ = tanhf(gg), o_ = sigf(go);
    float c = f_ * g_c[idx] + i_ * g_;
    float h = o_ * tanhf(c);
    g_c[idx] = c;
    g_h[idx] = h;
    g_seq[(size_t)(b * TT + t + 1) * EMB + j] = h;
}

// ---------------- launch ---------------------------------------------------
extern "C" void kernel_launch(void* const* d_in, const int* in_sizes, int n_in,
                              void* d_out, int out_size) {
    const float* features = (const float*)d_in[0];
    const int*   captions = (const int*)d_in[1];
    const float* W_emb    = (const float*)d_in[2];
    const float* W_out    = (const float*)d_in[3];
    const float* b_out    = (const float*)d_in[4];
    const float* W_ih     = (const float*)d_in[5];
    const float* W_hh     = (const float*)d_in[6];
    const float* b_ih     = (const float*)d_in[7];
    const float* b_hh     = (const float*)d_in[8];
    float* out = (float*)d_out;

    float *px, *pseq, *pxg, *pbias2;
    __nv_bfloat16 *pxa, *pseqa, *pwih3, *pwout3;
    cudaGetSymbolAddress((void**)&px,     g_x);
    cudaGetSymbolAddress((void**)&pseq,   g_seq);
    cudaGetSymbolAddress((void**)&pxg,    g_xg);
    cudaGetSymbolAddress((void**)&pbias2, g_bias2);
    cudaGetSymbolAddress((void**)&pxa,    g_xa);
    cudaGetSymbolAddress((void**)&pseqa,  g_seqa);
    cudaGetSymbolAddress((void**)&pwih3,  g_wih3);
    cudaGetSymbolAddress((void**)&pwout3, g_wout3);

    const int SMEM_MMA = 3 * 32768 + 256;   // 98560
    cudaFuncSetAttribute(mma_gemm, cudaFuncAttributeMaxDynamicSharedMemorySize, SMEM_MMA);

    // prep
    k_embed<<<(TS * BB * EMB + 255) / 256, 256>>>(W_emb, captions);
    k_init<<<(BB * EMB + 255) / 256, 256>>>(features);
    k_bias2<<<(G4 + 255) / 256, 256>>>(b_ih, b_hh);
    k_convert<<<(MR * EMB + 255) / 256, 256>>>(px, pxa, TS * BB, MR, 0);
    k_convert<<<(G4 * EMB + 255) / 256, 256>>>(W_ih, pwih3, G4, G4, 1);
    k_convert<<<(VOCAB * EMB + 255) / 256, 256>>>(W_out, pwout3, VOCAB, VOCAB, 1);

    // Xg = x @ W_ih^T + (b_ih + b_hh)   [M=1280, N=2048]
    mma_gemm<<<dim3(G4 / 128, MR / 128), 256, SMEM_MMA>>>(pxa, pwih3, pxg, G4, pbias2);

    // recurrence
    for (int t = 0; t < TS; t++) {
        k_step<<<128, 256>>>(W_hh);
        k_update<<<(BB * EMB + 255) / 256, 256>>>(t);
    }

    // logits = seq @ W_out^T + b_out    [M=1280, N=32000]
    k_convert<<<(MR * EMB + 255) / 256, 256>>>(pseq, pseqa, MR, MR, 0);
    mma_gemm<<<dim3(VOCAB / 128, MR / 128), 256, SMEM_MMA>>>(pseqa, pwout3, out, VOCAB, b_out);
}